// round 2
// baseline (speedup 1.0000x reference)
#include <cuda_runtime.h>
#include <cuda_bf16.h>
#include <stdint.h>

// Problem constants (SpectralSGCN2Layer): N=100000 nodes, D=128, E=1600000 edges.
#define MAX_N 100000
#define DIM   128

// Scratch for per-node gate scores (device globals: no allocation allowed).
__device__ float g_sdst[MAX_N];   // h[i,:] . gate_w[0:D]  + gate_b
__device__ float g_ssrc[MAX_N];   // h[i,:] . gate_w[D:2D]

// ---------------------------------------------------------------------------
// Kernel 1: per-node gate scores. One warp per node row.
// Each lane handles one float4 (4 of 128 dims), warp-reduce via shfl.
// ---------------------------------------------------------------------------
__global__ void node_scores_kernel(const float* __restrict__ h,
                                   const float* __restrict__ gate_w,
                                   const float* __restrict__ gate_b,
                                   int n)
{
    int warp_in_block = threadIdx.x >> 5;
    int lane = threadIdx.x & 31;
    int row = blockIdx.x * (blockDim.x >> 5) + warp_in_block;
    if (row >= n) return;

    const float4 hv = reinterpret_cast<const float4*>(h)[row * (DIM / 4) + lane];
    const float4 wd = reinterpret_cast<const float4*>(gate_w)[lane];        // w_dst
    const float4 ws = reinterpret_cast<const float4*>(gate_w)[32 + lane];   // w_src

    float sd = hv.x * wd.x + hv.y * wd.y + hv.z * wd.z + hv.w * wd.w;
    float ss = hv.x * ws.x + hv.y * ws.y + hv.z * ws.z + hv.w * ws.w;

    #pragma unroll
    for (int off = 16; off > 0; off >>= 1) {
        sd += __shfl_xor_sync(0xFFFFFFFFu, sd, off);
        ss += __shfl_xor_sync(0xFFFFFFFFu, ss, off);
    }

    if (lane == 0) {
        g_sdst[row] = sd + gate_b[0];
        g_ssrc[row] = ss;
    }
}

// ---------------------------------------------------------------------------
// Kernel 2: per-edge gather-scale-scatter. One warp per edge.
// Lane l loads h[src][4l:4l+4] as float4, scales, and does a vector
// red.global.add.v4.f32 into z[dst][4l:4l+4].
// Indices are int32 (JAX x64 disabled -> jnp.int64 is silently int32).
// ---------------------------------------------------------------------------
__global__ void edge_scatter_kernel(const float* __restrict__ h,
                                    const float* __restrict__ d,
                                    const float* __restrict__ w,
                                    const int* __restrict__ src,
                                    const int* __restrict__ dst,
                                    float* __restrict__ z,
                                    int num_edges,
                                    int n)
{
    int lane = threadIdx.x & 31;
    int e = blockIdx.x * (blockDim.x >> 5) + (threadIdx.x >> 5);
    if (e >= num_edges) return;

    // Uniform (broadcast) per-edge scalar loads. Clamp defensively so a
    // dtype surprise produces a wrong answer (diagnosable) instead of a crash.
    int s = __ldg(&src[e]);
    int t = __ldg(&dst[e]);
    s = min(max(s, 0), n - 1);
    t = min(max(t, 0), n - 1);

    const float alpha = tanhf(g_sdst[t] + g_ssrc[s]);
    const float coef  = alpha * __ldg(&d[t]) * __ldg(&d[s]) * __ldg(&w[e]);

    // Coalesced 512B gather of h[src] row.
    float4 v = __ldg(&reinterpret_cast<const float4*>(h)[(size_t)s * (DIM / 4) + lane]);
    v.x *= coef; v.y *= coef; v.z *= coef; v.w *= coef;

    // Vector fp32 reduction into z[dst] row (16B per lane, no return).
    float* p = z + (size_t)t * DIM + lane * 4;
    asm volatile("red.global.add.v4.f32 [%0], {%1, %2, %3, %4};"
                 :: "l"(p), "f"(v.x), "f"(v.y), "f"(v.z), "f"(v.w)
                 : "memory");
}

// ---------------------------------------------------------------------------
// Launch. Inputs (metadata order): h[N*D] f32, d[N] f32, w[E] f32,
// gate_w[2D] f32, gate_b[1] f32, src[E] i32, dst[E] i32. Output z[N*D] f32.
// ---------------------------------------------------------------------------
extern "C" void kernel_launch(void* const* d_in, const int* in_sizes, int n_in,
                              void* d_out, int out_size)
{
    const float* h      = (const float*)d_in[0];
    const float* d      = (const float*)d_in[1];
    const float* w      = (const float*)d_in[2];
    const float* gate_w = (const float*)d_in[3];
    const float* gate_b = (const float*)d_in[4];
    const int*   src    = (const int*)d_in[5];
    const int*   dst    = (const int*)d_in[6];
    float*       z      = (float*)d_out;

    const int n = in_sizes[1];      // N (elements of d)
    const int E = in_sizes[2];      // E (elements of w)

    // Zero output (it is poisoned before timing).
    cudaMemsetAsync(d_out, 0, (size_t)out_size * sizeof(float));

    // Kernel 1: 8 warps/block -> one node per warp.
    {
        const int threads = 256;
        const int warps_per_block = threads / 32;
        const int blocks = (n + warps_per_block - 1) / warps_per_block;
        node_scores_kernel<<<blocks, threads>>>(h, gate_w, gate_b, n);
    }

    // Kernel 2: 8 warps/block -> one edge per warp.
    {
        const int threads = 256;
        const int warps_per_block = threads / 32;
        const int blocks = (E + warps_per_block - 1) / warps_per_block;
        edge_scatter_kernel<<<blocks, threads>>>(h, d, w, src, dst, z, E, n);
    }
}

// round 3
// speedup vs baseline: 1.8761x; 1.8761x over previous
#include <cuda_runtime.h>
#include <cuda_bf16.h>
#include <stdint.h>

// Problem constants: N=100000 nodes, D=128, E=1600000 edges.
#define MAX_N 100000
#define MAX_E 1600000
#define DIM   128
#define SCAN_TILE 1024
#define MAX_TILES ((MAX_N + SCAN_TILE - 1) / SCAN_TILE)   // 98

// Device-global scratch (no allocation allowed).
__device__ float2 g_sd2[MAX_N];          // {h.w_dst + b, d[i]}
__device__ float2 g_ss2[MAX_N];          // {h.w_src,     d[i]}
__device__ int    g_counts[MAX_N];       // per-dst degree
__device__ int    g_offsets[MAX_N];      // exclusive scan of counts
__device__ int    g_cursor[MAX_N];       // scatter cursors (copy of offsets)
__device__ int    g_tilesums[MAX_TILES]; // scan tile totals
__device__ float2 g_es[MAX_E];           // dst-sorted edges: {bitcast(src), coef}

// ---------------------------------------------------------------------------
// 1. Per-node gate scores, packed with d[i]. One warp per node.
// ---------------------------------------------------------------------------
__global__ void node_scores_kernel(const float* __restrict__ h,
                                   const float* __restrict__ d,
                                   const float* __restrict__ gate_w,
                                   const float* __restrict__ gate_b,
                                   int n)
{
    int lane = threadIdx.x & 31;
    int row = blockIdx.x * (blockDim.x >> 5) + (threadIdx.x >> 5);
    if (row >= n) return;

    const float4 hv = reinterpret_cast<const float4*>(h)[row * (DIM / 4) + lane];
    const float4 wd = reinterpret_cast<const float4*>(gate_w)[lane];
    const float4 ws = reinterpret_cast<const float4*>(gate_w)[32 + lane];

    float sd = hv.x * wd.x + hv.y * wd.y + hv.z * wd.z + hv.w * wd.w;
    float ss = hv.x * ws.x + hv.y * ws.y + hv.z * ws.z + hv.w * ws.w;

    #pragma unroll
    for (int off = 16; off > 0; off >>= 1) {
        sd += __shfl_xor_sync(0xFFFFFFFFu, sd, off);
        ss += __shfl_xor_sync(0xFFFFFFFFu, ss, off);
    }

    if (lane == 0) {
        float di = __ldg(&d[row]);
        g_sd2[row] = make_float2(sd + gate_b[0], di);
        g_ss2[row] = make_float2(ss, di);
    }
}

// ---------------------------------------------------------------------------
// 2. Zero degree counters.
// ---------------------------------------------------------------------------
__global__ void zero_counts_kernel(int n)
{
    int i = blockIdx.x * blockDim.x + threadIdx.x;
    if (i < n) g_counts[i] = 0;
}

// ---------------------------------------------------------------------------
// 3. Histogram of dst.
// ---------------------------------------------------------------------------
__global__ void hist_kernel(const int* __restrict__ dst, int num_edges, int n)
{
    int e = blockIdx.x * blockDim.x + threadIdx.x;
    if (e >= num_edges) return;
    int t = __ldg(&dst[e]);
    t = min(max(t, 0), n - 1);
    atomicAdd(&g_counts[t], 1);
}

// ---------------------------------------------------------------------------
// 4a. Per-tile exclusive scan (tile = 1024).
// ---------------------------------------------------------------------------
__global__ void scan_tile_kernel(int n)
{
    __shared__ int buf[SCAN_TILE];
    int tid = threadIdx.x;
    int i = blockIdx.x * SCAN_TILE + tid;
    int v = (i < n) ? g_counts[i] : 0;
    buf[tid] = v;
    __syncthreads();
    for (int off = 1; off < SCAN_TILE; off <<= 1) {
        int t = buf[tid];
        if (tid >= off) t += buf[tid - off];
        __syncthreads();
        buf[tid] = t;
        __syncthreads();
    }
    int incl = buf[tid];
    if (i < n) g_offsets[i] = incl - v;      // exclusive, pre-base
    if (tid == SCAN_TILE - 1) g_tilesums[blockIdx.x] = incl;
}

// ---------------------------------------------------------------------------
// 4b. Scan of tile sums (single block; MAX_TILES <= 128).
// ---------------------------------------------------------------------------
__global__ void scan_sums_kernel(int ntiles)
{
    __shared__ int buf[128];
    int tid = threadIdx.x;
    int v = (tid < ntiles) ? g_tilesums[tid] : 0;
    buf[tid] = v;
    __syncthreads();
    for (int off = 1; off < 128; off <<= 1) {
        int t = buf[tid];
        if (tid >= off) t += buf[tid - off];
        __syncthreads();
        buf[tid] = t;
        __syncthreads();
    }
    if (tid < ntiles) g_tilesums[tid] = buf[tid] - v;  // exclusive
}

// ---------------------------------------------------------------------------
// 4c. Add tile base; initialize cursors.
// ---------------------------------------------------------------------------
__global__ void add_base_kernel(int n)
{
    int i = blockIdx.x * blockDim.x + threadIdx.x;
    if (i >= n) return;
    int off = g_offsets[i] + g_tilesums[i / SCAN_TILE];
    g_offsets[i] = off;
    g_cursor[i]  = off;
}

// ---------------------------------------------------------------------------
// 5. Scatter edges into dst-sorted order with fully-computed coefficient.
// ---------------------------------------------------------------------------
__global__ void scatter_kernel(const float* __restrict__ w,
                               const int* __restrict__ src,
                               const int* __restrict__ dst,
                               int num_edges, int n)
{
    int e = blockIdx.x * blockDim.x + threadIdx.x;
    if (e >= num_edges) return;
    int s = __ldg(&src[e]);
    int t = __ldg(&dst[e]);
    s = min(max(s, 0), n - 1);
    t = min(max(t, 0), n - 1);

    float2 a = g_sd2[t];   // {sdst+b, d[t]}
    float2 b = g_ss2[s];   // {ssrc,   d[s]}
    float coef = tanhf(a.x + b.x) * a.y * b.y * __ldg(&w[e]);

    int pos = atomicAdd(&g_cursor[t], 1);
    g_es[pos] = make_float2(__int_as_float(s), coef);
}

// ---------------------------------------------------------------------------
// 6. Gather-accumulate. One warp per dst node; lane = one float4 of the row.
//    Edge metadata loaded coalesced 32-at-a-time, then broadcast via shfl.
//    Writes each z row exactly once (also covers the poisoned-output init).
// ---------------------------------------------------------------------------
__global__ void gather_kernel(const float* __restrict__ h,
                              float* __restrict__ z,
                              int n)
{
    int lane = threadIdx.x & 31;
    int t = blockIdx.x * (blockDim.x >> 5) + (threadIdx.x >> 5);
    if (t >= n) return;

    const int start = g_offsets[t];
    const int deg   = g_counts[t];
    const float4* __restrict__ h4 = reinterpret_cast<const float4*>(h);

    float4 acc = make_float4(0.f, 0.f, 0.f, 0.f);

    for (int base = 0; base < deg; base += 32) {
        int j = base + lane;
        float2 m = (j < deg) ? g_es[start + j] : make_float2(0.f, 0.f);
        int   sj = __float_as_int(m.x);
        float cj = m.y;
        int cnt = min(32, deg - base);
        #pragma unroll 4
        for (int k = 0; k < cnt; k++) {
            int   s = __shfl_sync(0xFFFFFFFFu, sj, k);
            float c = __shfl_sync(0xFFFFFFFFu, cj, k);
            float4 hv = __ldg(&h4[(size_t)s * (DIM / 4) + lane]);
            acc.x += c * hv.x;
            acc.y += c * hv.y;
            acc.z += c * hv.z;
            acc.w += c * hv.w;
        }
    }

    reinterpret_cast<float4*>(z)[(size_t)t * (DIM / 4) + lane] = acc;
}

// ---------------------------------------------------------------------------
// Launch. Inputs: h[N*D] f32, d[N] f32, w[E] f32, gate_w[2D] f32,
// gate_b[1] f32, src[E] i32, dst[E] i32. Output z[N*D] f32.
// ---------------------------------------------------------------------------
extern "C" void kernel_launch(void* const* d_in, const int* in_sizes, int n_in,
                              void* d_out, int out_size)
{
    const float* h      = (const float*)d_in[0];
    const float* d      = (const float*)d_in[1];
    const float* w      = (const float*)d_in[2];
    const float* gate_w = (const float*)d_in[3];
    const float* gate_b = (const float*)d_in[4];
    const int*   src    = (const int*)d_in[5];
    const int*   dst    = (const int*)d_in[6];
    float*       z      = (float*)d_out;

    const int n = in_sizes[1];      // N
    const int E = in_sizes[2];      // E
    const int ntiles = (n + SCAN_TILE - 1) / SCAN_TILE;

    // 1. Gate scores (one warp per node; 8 warps/block).
    node_scores_kernel<<<(n + 7) / 8, 256>>>(h, d, gate_w, gate_b, n);

    // 2-4. Degree histogram + exclusive scan.
    zero_counts_kernel<<<(n + 255) / 256, 256>>>(n);
    hist_kernel<<<(E + 255) / 256, 256>>>(dst, E, n);
    scan_tile_kernel<<<ntiles, SCAN_TILE>>>(n);
    scan_sums_kernel<<<1, 128>>>(ntiles);
    add_base_kernel<<<(n + 255) / 256, 256>>>(n);

    // 5. Scatter edges into dst-sorted (src, coef) pairs.
    scatter_kernel<<<(E + 255) / 256, 256>>>(w, src, dst, E, n);

    // 6. Register-accumulated segment sum; writes every z row once.
    gather_kernel<<<(n + 7) / 8, 256>>>(h, z, n);
}

// round 4
// speedup vs baseline: 2.1638x; 1.1533x over previous
#include <cuda_runtime.h>
#include <cuda_fp16.h>
#include <stdint.h>

// Problem constants: N=100000 nodes, D=128, E=1600000 edges.
#define MAX_N 100000
#define MAX_E 1600000
#define DIM   128
#define SCAN_TILE 1024
#define MAX_TILES ((MAX_N + SCAN_TILE - 1) / SCAN_TILE)   // 98

// Device-global scratch (no allocation allowed).
__device__ float2 g_sd2[MAX_N];           // {h.w_dst + b, d[i]}
__device__ float2 g_ss2[MAX_N];           // {h.w_src,     d[i]}
__device__ int    g_counts[MAX_N];        // per-dst degree
__device__ int    g_offsets[MAX_N];       // exclusive scan of counts
__device__ int    g_cursor[MAX_N];        // scatter cursors
__device__ int    g_tilesums[MAX_TILES];  // scan tile totals
__device__ float2 g_es[MAX_E];            // dst-sorted edges: {bitcast(src), coef}
__device__ __half g_hh[(size_t)MAX_N * DIM]; // fp16 replica of h (gather path)

// ---------------------------------------------------------------------------
// 1. Per-node gate scores + fp16 conversion of h. One warp per node.
//    Lane l owns dims [4l, 4l+4): reads float4, writes 4 halves (8B).
// ---------------------------------------------------------------------------
__global__ void node_scores_kernel(const float* __restrict__ h,
                                   const float* __restrict__ d,
                                   const float* __restrict__ gate_w,
                                   const float* __restrict__ gate_b,
                                   int n)
{
    int lane = threadIdx.x & 31;
    int row = blockIdx.x * (blockDim.x >> 5) + (threadIdx.x >> 5);
    if (row >= n) return;

    const float4 hv = reinterpret_cast<const float4*>(h)[(size_t)row * (DIM / 4) + lane];
    const float4 wd = reinterpret_cast<const float4*>(gate_w)[lane];
    const float4 ws = reinterpret_cast<const float4*>(gate_w)[32 + lane];

    // fp16 replica (coalesced 8B per lane).
    __half2 p01 = __floats2half2_rn(hv.x, hv.y);
    __half2 p23 = __floats2half2_rn(hv.z, hv.w);
    uint2 packed;
    packed.x = *reinterpret_cast<uint32_t*>(&p01);
    packed.y = *reinterpret_cast<uint32_t*>(&p23);
    reinterpret_cast<uint2*>(g_hh)[(size_t)row * 32 + lane] = packed;

    float sd = hv.x * wd.x + hv.y * wd.y + hv.z * wd.z + hv.w * wd.w;
    float ss = hv.x * ws.x + hv.y * ws.y + hv.z * ws.z + hv.w * ws.w;

    #pragma unroll
    for (int off = 16; off > 0; off >>= 1) {
        sd += __shfl_xor_sync(0xFFFFFFFFu, sd, off);
        ss += __shfl_xor_sync(0xFFFFFFFFu, ss, off);
    }

    if (lane == 0) {
        float di = __ldg(&d[row]);
        g_sd2[row] = make_float2(sd + gate_b[0], di);
        g_ss2[row] = make_float2(ss, di);
    }
}

// ---------------------------------------------------------------------------
// 2. Histogram of dst (counts zeroed by cudaMemsetAsync).
// ---------------------------------------------------------------------------
__global__ void hist_kernel(const int* __restrict__ dst, int num_edges, int n)
{
    int e = blockIdx.x * blockDim.x + threadIdx.x;
    if (e >= num_edges) return;
    int t = __ldg(&dst[e]);
    t = min(max(t, 0), n - 1);
    atomicAdd(&g_counts[t], 1);
}

// ---------------------------------------------------------------------------
// 3a. Per-tile exclusive scan (tile = 1024).
// ---------------------------------------------------------------------------
__global__ void scan_tile_kernel(int n)
{
    __shared__ int buf[SCAN_TILE];
    int tid = threadIdx.x;
    int i = blockIdx.x * SCAN_TILE + tid;
    int v = (i < n) ? g_counts[i] : 0;
    buf[tid] = v;
    __syncthreads();
    for (int off = 1; off < SCAN_TILE; off <<= 1) {
        int t = buf[tid];
        if (tid >= off) t += buf[tid - off];
        __syncthreads();
        buf[tid] = t;
        __syncthreads();
    }
    int incl = buf[tid];
    if (i < n) g_offsets[i] = incl - v;      // exclusive, pre-base
    if (tid == SCAN_TILE - 1) g_tilesums[blockIdx.x] = incl;
}

// ---------------------------------------------------------------------------
// 3b. Scan of tile sums (single block; MAX_TILES <= 128).
// ---------------------------------------------------------------------------
__global__ void scan_sums_kernel(int ntiles)
{
    __shared__ int buf[128];
    int tid = threadIdx.x;
    int v = (tid < ntiles) ? g_tilesums[tid] : 0;
    buf[tid] = v;
    __syncthreads();
    for (int off = 1; off < 128; off <<= 1) {
        int t = buf[tid];
        if (tid >= off) t += buf[tid - off];
        __syncthreads();
        buf[tid] = t;
        __syncthreads();
    }
    if (tid < ntiles) g_tilesums[tid] = buf[tid] - v;  // exclusive
}

// ---------------------------------------------------------------------------
// 3c. Add tile base; initialize cursors.
// ---------------------------------------------------------------------------
__global__ void add_base_kernel(int n)
{
    int i = blockIdx.x * blockDim.x + threadIdx.x;
    if (i >= n) return;
    int off = g_offsets[i] + g_tilesums[i / SCAN_TILE];
    g_offsets[i] = off;
    g_cursor[i]  = off;
}

// ---------------------------------------------------------------------------
// 4. Scatter edges into dst-sorted order with fully-computed coefficient.
// ---------------------------------------------------------------------------
__global__ void scatter_kernel(const float* __restrict__ w,
                               const int* __restrict__ src,
                               const int* __restrict__ dst,
                               int num_edges, int n)
{
    int e = blockIdx.x * blockDim.x + threadIdx.x;
    if (e >= num_edges) return;
    int s = __ldg(&src[e]);
    int t = __ldg(&dst[e]);
    s = min(max(s, 0), n - 1);
    t = min(max(t, 0), n - 1);

    float2 a = g_sd2[t];   // {sdst+b, d[t]}
    float2 b = g_ss2[s];   // {ssrc,   d[s]}
    float coef = tanhf(a.x + b.x) * a.y * b.y * __ldg(&w[e]);

    int pos = atomicAdd(&g_cursor[t], 1);
    g_es[pos] = make_float2(__int_as_float(s), coef);
}

// ---------------------------------------------------------------------------
// 5. Gather-accumulate from fp16 h replica. One warp per dst node.
//    Lane l owns dims [4l, 4l+4): one 8B load per edge (256B/row/warp).
//    Accumulation in fp32. Writes each z row exactly once.
// ---------------------------------------------------------------------------
__global__ void gather_kernel(float* __restrict__ z, int n)
{
    int lane = threadIdx.x & 31;
    int t = blockIdx.x * (blockDim.x >> 5) + (threadIdx.x >> 5);
    if (t >= n) return;

    const int start = g_offsets[t];
    const int deg   = g_counts[t];
    const uint2* __restrict__ h2 = reinterpret_cast<const uint2*>(g_hh);

    float4 acc = make_float4(0.f, 0.f, 0.f, 0.f);

    for (int base = 0; base < deg; base += 32) {
        int j = base + lane;
        float2 m = (j < deg) ? g_es[start + j] : make_float2(0.f, 0.f);
        int   sj = __float_as_int(m.x);
        float cj = m.y;
        int cnt = min(32, deg - base);
        #pragma unroll 4
        for (int k = 0; k < cnt; k++) {
            int   s = __shfl_sync(0xFFFFFFFFu, sj, k);
            float c = __shfl_sync(0xFFFFFFFFu, cj, k);
            uint2 hv = __ldg(&h2[(size_t)s * 32 + lane]);
            float2 f01 = __half22float2(*reinterpret_cast<__half2*>(&hv.x));
            float2 f23 = __half22float2(*reinterpret_cast<__half2*>(&hv.y));
            acc.x += c * f01.x;
            acc.y += c * f01.y;
            acc.z += c * f23.x;
            acc.w += c * f23.y;
        }
    }

    reinterpret_cast<float4*>(z)[(size_t)t * (DIM / 4) + lane] = acc;
}

// ---------------------------------------------------------------------------
// Launch. Inputs: h[N*D] f32, d[N] f32, w[E] f32, gate_w[2D] f32,
// gate_b[1] f32, src[E] i32, dst[E] i32. Output z[N*D] f32.
// ---------------------------------------------------------------------------
extern "C" void kernel_launch(void* const* d_in, const int* in_sizes, int n_in,
                              void* d_out, int out_size)
{
    const float* h      = (const float*)d_in[0];
    const float* d      = (const float*)d_in[1];
    const float* w      = (const float*)d_in[2];
    const float* gate_w = (const float*)d_in[3];
    const float* gate_b = (const float*)d_in[4];
    const int*   src    = (const int*)d_in[5];
    const int*   dst    = (const int*)d_in[6];
    float*       z      = (float*)d_out;

    const int n = in_sizes[1];      // N
    const int E = in_sizes[2];      // E
    const int ntiles = (n + SCAN_TILE - 1) / SCAN_TILE;

    // Zero degree counters via memset (graph-capturable, no alloc).
    void* counts_ptr = nullptr;
    cudaGetSymbolAddress(&counts_ptr, g_counts);
    cudaMemsetAsync(counts_ptr, 0, (size_t)n * sizeof(int));

    // 1. Gate scores + fp16 h conversion (one warp per node).
    node_scores_kernel<<<(n + 7) / 8, 256>>>(h, d, gate_w, gate_b, n);

    // 2-3. Degree histogram + exclusive scan.
    hist_kernel<<<(E + 255) / 256, 256>>>(dst, E, n);
    scan_tile_kernel<<<ntiles, SCAN_TILE>>>(n);
    scan_sums_kernel<<<1, 128>>>(ntiles);
    add_base_kernel<<<(n + 255) / 256, 256>>>(n);

    // 4. Scatter edges into dst-sorted (src, coef) pairs.
    scatter_kernel<<<(E + 255) / 256, 256>>>(w, src, dst, E, n);

    // 5. Register-accumulated segment sum; writes every z row once.
    gather_kernel<<<(n + 7) / 8, 256>>>(z, n);
}